// round 7
// baseline (speedup 1.0000x reference)
#include <cuda_runtime.h>
#include <cuda_bf16.h>
#include <cstdint>

#define NUM_E 1024
#define EDIM  256
#define NROWS 32768

// ---- device scratch ----
__device__ float g_cbnorm[NUM_E];
__device__ float g_cbT[EDIM * NUM_E];
__device__ unsigned long long g_key[NROWS];        // (ordfloat<<32)|idx
__device__ __nv_bfloat16 g_bsp[3][NUM_E * EDIM];   // codebook bf16 splits [sp][n][c]
// pre-split z, tiled: [mtile 256][ch 8][sp 3][cr 32][m 128] bf16 (50 MB)
__device__ __nv_bfloat16 g_zsp[256 * 8 * 3 * 32 * 128];

// ---- smem layout (bytes) ----
#define AS_STRIDE 272                // 128 m * 2B + 16 pad (conflict-free ldsm)
#define AS_SPLIT  (32 * AS_STRIDE)   // 8704
#define AS_BUF    (3 * AS_SPLIT)     // 26112
#define BS_OFF    (2 * AS_BUF)       // 52224
#define BS_STRIDE 80
#define BS_SPLIT  (128 * BS_STRIDE)  // 10240
#define BS_BUF    (3 * BS_SPLIT)     // 30720
#define SMEM_TOTAL (BS_OFF + 2 * BS_BUF)  // 113664 -> 2 CTAs/SM

__device__ __forceinline__ uint32_t smem_u32(const void* p) {
    uint32_t a;
    asm("{ .reg .u64 t; cvta.to.shared.u64 t, %1; cvt.u32.u64 %0, t; }" : "=r"(a) : "l"(p));
    return a;
}
__device__ __forceinline__ void cpasync16(uint32_t dst, const void* src) {
    asm volatile("cp.async.cg.shared.global [%0], [%1], 16;" :: "r"(dst), "l"(src));
}
__device__ __forceinline__ void ldsm_x4(uint32_t* r, uint32_t addr) {
    asm volatile("ldmatrix.sync.aligned.m8n8.x4.shared.b16 {%0,%1,%2,%3}, [%4];"
                 : "=r"(r[0]), "=r"(r[1]), "=r"(r[2]), "=r"(r[3]) : "r"(addr));
}
__device__ __forceinline__ void ldsm_x4t(uint32_t* r, uint32_t addr) {
    asm volatile("ldmatrix.sync.aligned.m8n8.x4.trans.shared.b16 {%0,%1,%2,%3}, [%4];"
                 : "=r"(r[0]), "=r"(r[1]), "=r"(r[2]), "=r"(r[3]) : "r"(addr));
}
__device__ __forceinline__ void mma16816(float* c, const uint32_t* a, uint32_t b0, uint32_t b1) {
    asm volatile("mma.sync.aligned.m16n8k16.row.col.f32.bf16.bf16.f32 "
                 "{%0,%1,%2,%3}, {%4,%5,%6,%7}, {%8,%9}, {%0,%1,%2,%3};"
                 : "+f"(c[0]), "+f"(c[1]), "+f"(c[2]), "+f"(c[3])
                 : "r"(a[0]), "r"(a[1]), "r"(a[2]), "r"(a[3]), "r"(b0), "r"(b1));
}
__device__ __forceinline__ unsigned ordf(float d) {
    unsigned u = __float_as_uint(d);
    return (u & 0x80000000u) ? ~u : (u | 0x80000000u);
}

// ---------- prep 1: codebook norms + transpose + bf16 splits + key init ----------
__global__ __launch_bounds__(256) void prep_kernel(const float* __restrict__ cb) {
    int k = blockIdx.x, t = threadIdx.x;
    float v = cb[(size_t)k * EDIM + t];
    g_cbT[(size_t)t * NUM_E + k] = v;
    __nv_bfloat16 s0 = __float2bfloat16(v);  float r1 = v - __bfloat162float(s0);
    __nv_bfloat16 s1 = __float2bfloat16(r1); float r2 = r1 - __bfloat162float(s1);
    __nv_bfloat16 s2 = __float2bfloat16(r2);
    g_bsp[0][k * EDIM + t] = s0;
    g_bsp[1][k * EDIM + t] = s1;
    g_bsp[2][k * EDIM + t] = s2;
    if (t < 32) g_key[k * 32 + t] = ~0ull;
    float sq = v * v;
    #pragma unroll
    for (int o = 16; o; o >>= 1) sq += __shfl_down_sync(0xffffffffu, sq, o);
    __shared__ float ws[8];
    if ((t & 31) == 0) ws[t >> 5] = sq;
    __syncthreads();
    if (t == 0) {
        float s = 0.f;
        #pragma unroll
        for (int i = 0; i < 8; i++) s += ws[i];
        g_cbnorm[k] = s;
    }
}

// ---------- prep 2: z -> 3 bf16 splits, tiled layout ----------
// grid 2048: bid -> (mtile = bid>>3, ch = bid&7); block 256
__global__ __launch_bounds__(256) void prep_z_kernel(const float* __restrict__ z) {
    const int bid = blockIdx.x, t = threadIdx.x;
    const int mtile = bid >> 3, ch = bid & 7;
    const int cr = t >> 3, ms = (t & 7) * 16;
    const int m0 = mtile * 128;
    const float* src = z + ((size_t)(m0 >> 10) << 18) + (size_t)(ch * 32 + cr) * 1024 + (m0 & 1023) + ms;
    __nv_bfloat16* dst0 = g_zsp + ((size_t)(bid * 3 + 0) * 32 + cr) * 128 + ms;
    __nv_bfloat16* dst1 = g_zsp + ((size_t)(bid * 3 + 1) * 32 + cr) * 128 + ms;
    __nv_bfloat16* dst2 = g_zsp + ((size_t)(bid * 3 + 2) * 32 + cr) * 128 + ms;
    uint32_t o0[8], o1[8], o2[8];
    #pragma unroll
    for (int q = 0; q < 4; q++) {
        float4 f = ((const float4*)src)[q];
        float xs[4] = {f.x, f.y, f.z, f.w};
        __nv_bfloat16 p0[4], p1[4], p2[4];
        #pragma unroll
        for (int e = 0; e < 4; e++) {
            p0[e] = __float2bfloat16(xs[e]); float r = xs[e] - __bfloat162float(p0[e]);
            p1[e] = __float2bfloat16(r);     r = r - __bfloat162float(p1[e]);
            p2[e] = __float2bfloat16(r);
        }
        __nv_bfloat162 v;
        v = __halves2bfloat162(p0[0], p0[1]); o0[q * 2]     = *(uint32_t*)&v;
        v = __halves2bfloat162(p0[2], p0[3]); o0[q * 2 + 1] = *(uint32_t*)&v;
        v = __halves2bfloat162(p1[0], p1[1]); o1[q * 2]     = *(uint32_t*)&v;
        v = __halves2bfloat162(p1[2], p1[3]); o1[q * 2 + 1] = *(uint32_t*)&v;
        v = __halves2bfloat162(p2[0], p2[1]); o2[q * 2]     = *(uint32_t*)&v;
        v = __halves2bfloat162(p2[2], p2[3]); o2[q * 2 + 1] = *(uint32_t*)&v;
    }
    ((uint4*)dst0)[0] = *(uint4*)&o0[0]; ((uint4*)dst0)[1] = *(uint4*)&o0[4];
    ((uint4*)dst1)[0] = *(uint4*)&o1[0]; ((uint4*)dst1)[1] = *(uint4*)&o1[4];
    ((uint4*)dst2)[0] = *(uint4*)&o2[0]; ((uint4*)dst2)[1] = *(uint4*)&o2[4];
}

// ---- async tile loaders ----
__device__ __forceinline__ void issue_A(uint32_t dst, int mtile, int ch, int tid) {
    #pragma unroll
    for (int r = 0; r < 6; r++) {
        int e = tid + r * 256;
        int seg = e & 15, rowq = e >> 4;
        int cr = rowq & 31, sp = rowq >> 5;
        cpasync16(dst + sp * AS_SPLIT + cr * AS_STRIDE + seg * 16,
                  g_zsp + ((size_t)((mtile * 8 + ch) * 3 + sp) * 32 + cr) * 128 + seg * 8);
    }
}
__device__ __forceinline__ void issue_B(uint32_t dst, int n0, int c0, int tid) {
    #pragma unroll
    for (int r = 0; r < 6; r++) {
        int e = tid + r * 256;
        int seg = e & 3, rowq = e >> 2;
        int bn = rowq & 127, q = rowq >> 7;
        cpasync16(dst + q * BS_SPLIT + bn * BS_STRIDE + seg * 16,
                  &g_bsp[q][(size_t)(n0 + bn) * EDIM + c0 + seg * 8]);
    }
}

// ---------- main: bf16 mma.sync GEMM + fused argmin ----------
// grid = 2048 (256 mtiles x 8 ntiles), block = 256, 2 CTAs/SM
__global__ __launch_bounds__(256, 2) void vq_mma_kernel() {
    extern __shared__ __align__(16) unsigned char smem[];
    const uint32_t sb = smem_u32(smem);
    const int tid = threadIdx.x;
    const int lane = tid & 31;
    const int w = tid >> 5, wm = w & 1, wn = w >> 1;   // 2 m-warps x 4 n-warps
    const int ntile = blockIdx.x & 7, mtile = blockIdx.x >> 3;
    const int m0 = mtile * 128, n0 = ntile * 128;

    float acc[4][4][4];
    #pragma unroll
    for (int i = 0; i < 4; i++)
        #pragma unroll
        for (int j = 0; j < 4; j++)
            #pragma unroll
            for (int e = 0; e < 4; e++) acc[i][j][e] = 0.f;

    // prologue: chunk 0 copies
    issue_A(sb, mtile, 0, tid);
    issue_B(sb + BS_OFF, n0, 0, tid);
    asm volatile("cp.async.commit_group;");

    const int sel = lane >> 3, rr = lane & 7;
    #pragma unroll 1
    for (int ch = 0; ch < 8; ch++) {
        const int buf = ch & 1;
        if (ch < 7) {
            const int nbuf = buf ^ 1;
            issue_A(sb + nbuf * AS_BUF, mtile, ch + 1, tid);
            issue_B(sb + BS_OFF + nbuf * BS_BUF, n0, (ch + 1) * 32, tid);
            asm volatile("cp.async.commit_group;");
            asm volatile("cp.async.wait_group 1;");
        } else {
            asm volatile("cp.async.wait_group 0;");
        }
        __syncthreads();

        const uint32_t asB = sb + buf * AS_BUF;
        const uint32_t bsB = sb + BS_OFF + buf * BS_BUF;
        #pragma unroll
        for (int ks = 0; ks < 2; ks++) {
            const int k0 = ks * 16;
            uint32_t bb[3][8];
            #pragma unroll
            for (int bj = 0; bj < 3; bj++) {
                uint32_t addr = bsB + bj * BS_SPLIT
                              + (wn * 32 + (sel >> 1) * 8 + rr) * BS_STRIDE
                              + (k0 + (sel & 1) * 8) * 2;
                ldsm_x4(bb[bj], addr);
                ldsm_x4(bb[bj] + 4, addr + 16 * BS_STRIDE);
            }
            #pragma unroll
            for (int ai = 0; ai < 3; ai++) {
                const int nbj = 3 - ai;
                #pragma unroll
                for (int i = 0; i < 4; i++) {
                    uint32_t a[4];
                    uint32_t addr = asB + ai * AS_SPLIT
                                  + (k0 + (sel >> 1) * 8 + rr) * AS_STRIDE
                                  + (wm * 64 + i * 16 + (sel & 1) * 8) * 2;
                    ldsm_x4t(a, addr);
                    #pragma unroll
                    for (int bj = 0; bj < 3; bj++) {
                        if (bj >= nbj) break;
                        #pragma unroll
                        for (int j = 0; j < 4; j++)
                            mma16816(acc[i][j], a, bb[bj][2 * j], bb[bj][2 * j + 1]);
                    }
                }
            }
        }
        __syncthreads();
    }

    // ---- epilogue: distances + argmin (kred aliases A buffer region) ----
    const int g = lane >> 2, tg = lane & 3;
    float cbn[8];
    #pragma unroll
    for (int j = 0; j < 4; j++) {
        cbn[2 * j]     = __ldg(&g_cbnorm[n0 + wn * 32 + j * 8 + tg * 2]);
        cbn[2 * j + 1] = __ldg(&g_cbnorm[n0 + wn * 32 + j * 8 + tg * 2 + 1]);
    }
    unsigned long long* kred = (unsigned long long*)smem;
    #pragma unroll
    for (int i = 0; i < 4; i++) {
        #pragma unroll
        for (int h = 0; h < 2; h++) {
            float best = 3.4e38f; int bidx = 0;
            #pragma unroll
            for (int j = 0; j < 4; j++) {
                float d0 = cbn[2 * j]     - 2.0f * acc[i][j][h * 2];
                float d1 = cbn[2 * j + 1] - 2.0f * acc[i][j][h * 2 + 1];
                int c = n0 + wn * 32 + j * 8 + tg * 2;
                if (d0 < best) { best = d0; bidx = c; }
                if (d1 < best) { best = d1; bidx = c + 1; }
            }
            unsigned long long key = ((unsigned long long)ordf(best) << 32) | (unsigned)bidx;
            #pragma unroll
            for (int off = 1; off <= 2; off <<= 1) {
                unsigned long long o = __shfl_down_sync(0xffffffffu, key, off, 4);
                if (o < key) key = o;
            }
            if (tg == 0) kred[(wm * 64 + i * 16 + h * 8 + g) * 4 + wn] = key;
        }
    }
    __syncthreads();
    if (tid < 128) {
        unsigned long long k = kred[tid * 4];
        #pragma unroll
        for (int q = 1; q < 4; q++) {
            unsigned long long o = kred[tid * 4 + q];
            if (o < k) k = o;
        }
        atomicMin(&g_key[m0 + tid], k);
    }
}

// ---------- merged outputs ----------
__global__ __launch_bounds__(256) void out_kernel(float* __restrict__ oh, float* __restrict__ oq) {
    int bid = blockIdx.x, t = threadIdx.x;
    if (bid < 32768) {
        int idx = (int)(g_key[bid] & 0xFFFFFFFFu);
        int c0 = t * 4;
        float4 v;
        v.x = (idx == c0) ? 1.f : 0.f; v.y = (idx == c0 + 1) ? 1.f : 0.f;
        v.z = (idx == c0 + 2) ? 1.f : 0.f; v.w = (idx == c0 + 3) ? 1.f : 0.f;
        *(float4*)&oh[(size_t)bid * NUM_E + c0] = v;
    } else {
        int i = (bid - 32768) * 256 + t;
        int flat = i * 4;
        int hw = flat & 1023, c = (flat >> 10) & 255, b = flat >> 18;
        int r0 = b * 1024 + hw;
        int4 idx4;
        idx4.x = (int)(g_key[r0] & 0xFFFFFFFFu);
        idx4.y = (int)(g_key[r0 + 1] & 0xFFFFFFFFu);
        idx4.z = (int)(g_key[r0 + 2] & 0xFFFFFFFFu);
        idx4.w = (int)(g_key[r0 + 3] & 0xFFFFFFFFu);
        const float* rowp = &g_cbT[(size_t)c * NUM_E];
        float4 v;
        v.x = rowp[idx4.x]; v.y = rowp[idx4.y]; v.z = rowp[idx4.z]; v.w = rowp[idx4.w];
        *(float4*)&oq[flat] = v;
    }
}

extern "C" void kernel_launch(void* const* d_in, const int* in_sizes, int n_in,
                              void* d_out, int out_size) {
    const float* z  = (const float*)d_in[0];
    const float* cb = (const float*)d_in[1];
    float* out_onehot = (float*)d_out;
    float* out_q      = (float*)d_out + (size_t)NROWS * NUM_E;

    cudaFuncSetAttribute(vq_mma_kernel, cudaFuncAttributeMaxDynamicSharedMemorySize, SMEM_TOTAL);
    prep_kernel<<<NUM_E, 256>>>(cb);
    prep_z_kernel<<<2048, 256>>>(z);
    vq_mma_kernel<<<2048, 256, SMEM_TOTAL>>>();
    out_kernel<<<40960, 256>>>(out_onehot, out_q);
}

// round 8
// speedup vs baseline: 1.5205x; 1.5205x over previous
#include <cuda_runtime.h>
#include <cuda_bf16.h>
#include <cstdint>

#define NUM_E 1024
#define EDIM  256
#define NROWS 32768

// ---- device scratch ----
__device__ float g_cbnorm[NUM_E];                  // ||e_k||^2
__device__ float g_cbT[EDIM * NUM_E];              // codebook transposed [c][k]
__device__ unsigned g_wmaxbits;                    // max ||e||^2 as float bits (nonneg)
__device__ int   g_idx[NROWS];                     // final argmin
__device__ __nv_bfloat16 g_b0[NUM_E * EDIM];       // bf16(codebook) [k][c]
__device__ __nv_bfloat16 g_z0[256 * 8 * 32 * 128]; // bf16(z) tiled [mtile][ch][cr][m]
__device__ __nv_bfloat16 g_dmat[(size_t)NROWS * NUM_E]; // approx distances (64MB)

// ---- smem layout for screen kernel (bytes) ----
#define AS_STRIDE 272                 // 128 m * 2B + 16 pad
#define AS_BUF    (32 * AS_STRIDE)    // 8704
#define BS_OFF    (2 * AS_BUF)        // 17408
#define BS_STRIDE 80
#define BS_BUF    (128 * BS_STRIDE)   // 10240
#define SMEM_TOTAL (BS_OFF + 2 * BS_BUF)  // 37888

__device__ __forceinline__ uint32_t smem_u32(const void* p) {
    uint32_t a;
    asm("{ .reg .u64 t; cvta.to.shared.u64 t, %1; cvt.u32.u64 %0, t; }" : "=r"(a) : "l"(p));
    return a;
}
__device__ __forceinline__ void cpasync16(uint32_t dst, const void* src) {
    asm volatile("cp.async.cg.shared.global [%0], [%1], 16;" :: "r"(dst), "l"(src));
}
__device__ __forceinline__ void ldsm_x4(uint32_t* r, uint32_t addr) {
    asm volatile("ldmatrix.sync.aligned.m8n8.x4.shared.b16 {%0,%1,%2,%3}, [%4];"
                 : "=r"(r[0]), "=r"(r[1]), "=r"(r[2]), "=r"(r[3]) : "r"(addr));
}
__device__ __forceinline__ void ldsm_x4t(uint32_t* r, uint32_t addr) {
    asm volatile("ldmatrix.sync.aligned.m8n8.x4.trans.shared.b16 {%0,%1,%2,%3}, [%4];"
                 : "=r"(r[0]), "=r"(r[1]), "=r"(r[2]), "=r"(r[3]) : "r"(addr));
}
__device__ __forceinline__ void mma16816(float* c, const uint32_t* a, uint32_t b0, uint32_t b1) {
    asm volatile("mma.sync.aligned.m16n8k16.row.col.f32.bf16.bf16.f32 "
                 "{%0,%1,%2,%3}, {%4,%5,%6,%7}, {%8,%9}, {%0,%1,%2,%3};"
                 : "+f"(c[0]), "+f"(c[1]), "+f"(c[2]), "+f"(c[3])
                 : "r"(a[0]), "r"(a[1]), "r"(a[2]), "r"(a[3]), "r"(b0), "r"(b1));
}
__device__ __forceinline__ unsigned ordf(float d) {
    unsigned u = __float_as_uint(d);
    return (u & 0x80000000u) ? ~u : (u | 0x80000000u);
}

// ---------- prep 1: codebook -> norms, transpose, bf16 image, max-norm ----------
__global__ __launch_bounds__(256) void prep_cb_kernel(const float* __restrict__ cb) {
    int k = blockIdx.x, t = threadIdx.x;
    float v = cb[(size_t)k * EDIM + t];
    g_cbT[(size_t)t * NUM_E + k] = v;
    g_b0[(size_t)k * EDIM + t] = __float2bfloat16(v);
    float sq = v * v;
    #pragma unroll
    for (int o = 16; o; o >>= 1) sq += __shfl_down_sync(0xffffffffu, sq, o);
    __shared__ float ws[8];
    if ((t & 31) == 0) ws[t >> 5] = sq;
    __syncthreads();
    if (t == 0) {
        float s = 0.f;
        #pragma unroll
        for (int i = 0; i < 8; i++) s += ws[i];
        g_cbnorm[k] = s;
        atomicMax(&g_wmaxbits, __float_as_uint(s));
    }
}

// ---------- prep 2: z -> bf16, tiled [mtile][ch][cr 32][m 128] ----------
__global__ __launch_bounds__(256) void prep_z_kernel(const float* __restrict__ z) {
    const int bid = blockIdx.x, t = threadIdx.x;     // bid = mtile*8 + ch
    const int mtile = bid >> 3, ch = bid & 7;
    const int cr = t >> 3, ms = (t & 7) * 16;
    const int m0 = mtile * 128;
    const float* src = z + ((size_t)(m0 >> 10) << 18) + (size_t)(ch * 32 + cr) * 1024 + (m0 & 1023) + ms;
    uint32_t o0[8];
    #pragma unroll
    for (int q = 0; q < 4; q++) {
        float4 f = ((const float4*)src)[q];
        __nv_bfloat162 v0 = __halves2bfloat162(__float2bfloat16(f.x), __float2bfloat16(f.y));
        __nv_bfloat162 v1 = __halves2bfloat162(__float2bfloat16(f.z), __float2bfloat16(f.w));
        o0[q * 2] = *(uint32_t*)&v0; o0[q * 2 + 1] = *(uint32_t*)&v1;
    }
    __nv_bfloat16* dst = g_z0 + ((size_t)bid * 32 + cr) * 128 + ms;
    ((uint4*)dst)[0] = *(uint4*)&o0[0];
    ((uint4*)dst)[1] = *(uint4*)&o0[4];
}

// ---- async tile loaders ----
__device__ __forceinline__ void issue_A(uint32_t dst, int mtile, int ch, int tid) {
    #pragma unroll
    for (int r = 0; r < 2; r++) {
        int e = tid + r * 256;
        int seg = e & 15, cr = e >> 4;
        cpasync16(dst + cr * AS_STRIDE + seg * 16,
                  g_z0 + ((size_t)(mtile * 8 + ch) * 32 + cr) * 128 + seg * 8);
    }
}
__device__ __forceinline__ void issue_B(uint32_t dst, int n0, int c0, int tid) {
    #pragma unroll
    for (int r = 0; r < 2; r++) {
        int e = tid + r * 256;
        int seg = e & 3, bn = e >> 2;
        cpasync16(dst + bn * BS_STRIDE + seg * 16,
                  g_b0 + (size_t)(n0 + bn) * EDIM + c0 + seg * 8);
    }
}

// ---------- screen: bf16 GEMM -> approx distance matrix (bf16) ----------
// grid = 2048 (256 mtiles x 8 ntiles), block = 256
__global__ __launch_bounds__(256, 2) void screen_kernel() {
    extern __shared__ __align__(16) unsigned char smem[];
    const uint32_t sb = smem_u32(smem);
    const int tid = threadIdx.x;
    const int lane = tid & 31;
    const int w = tid >> 5, wm = w & 1, wn = w >> 1;   // 2 m-warps x 4 n-warps
    const int ntile = blockIdx.x & 7, mtile = blockIdx.x >> 3;
    const int m0 = mtile * 128, n0 = ntile * 128;

    float acc[4][4][4];
    #pragma unroll
    for (int i = 0; i < 4; i++)
        #pragma unroll
        for (int j = 0; j < 4; j++)
            #pragma unroll
            for (int e = 0; e < 4; e++) acc[i][j][e] = 0.f;

    issue_A(sb, mtile, 0, tid);
    issue_B(sb + BS_OFF, n0, 0, tid);
    asm volatile("cp.async.commit_group;");

    const int sel = lane >> 3, rr = lane & 7;
    #pragma unroll 1
    for (int ch = 0; ch < 8; ch++) {
        const int buf = ch & 1;
        if (ch < 7) {
            const int nbuf = buf ^ 1;
            issue_A(sb + nbuf * AS_BUF, mtile, ch + 1, tid);
            issue_B(sb + BS_OFF + nbuf * BS_BUF, n0, (ch + 1) * 32, tid);
            asm volatile("cp.async.commit_group;");
            asm volatile("cp.async.wait_group 1;");
        } else {
            asm volatile("cp.async.wait_group 0;");
        }
        __syncthreads();

        const uint32_t asB = sb + buf * AS_BUF;
        const uint32_t bsB = sb + BS_OFF + buf * BS_BUF;
        #pragma unroll
        for (int ks = 0; ks < 2; ks++) {
            const int k0 = ks * 16;
            uint32_t bb[8];
            uint32_t baddr = bsB + (wn * 32 + (sel >> 1) * 8 + rr) * BS_STRIDE + (k0 + (sel & 1) * 8) * 2;
            ldsm_x4(bb, baddr);
            ldsm_x4(bb + 4, baddr + 16 * BS_STRIDE);
            #pragma unroll
            for (int i = 0; i < 4; i++) {
                uint32_t a[4];
                uint32_t aaddr = asB + (k0 + (sel >> 1) * 8 + rr) * AS_STRIDE
                               + (wm * 64 + i * 16 + (sel & 1) * 8) * 2;
                ldsm_x4t(a, aaddr);
                #pragma unroll
                for (int j = 0; j < 4; j++)
                    mma16816(acc[i][j], a, bb[2 * j], bb[2 * j + 1]);
            }
        }
        __syncthreads();
    }

    // epilogue: d~ = ||e||^2 - 2 s0, store bf16
    const int g = lane >> 2, tg = lane & 3;
    float cbn[8];
    #pragma unroll
    for (int j = 0; j < 4; j++) {
        cbn[2 * j]     = __ldg(&g_cbnorm[n0 + wn * 32 + j * 8 + tg * 2]);
        cbn[2 * j + 1] = __ldg(&g_cbnorm[n0 + wn * 32 + j * 8 + tg * 2 + 1]);
    }
    #pragma unroll
    for (int i = 0; i < 4; i++) {
        #pragma unroll
        for (int h = 0; h < 2; h++) {
            int row = m0 + wm * 64 + i * 16 + h * 8 + g;
            #pragma unroll
            for (int j = 0; j < 4; j++) {
                float d0 = cbn[2 * j]     - 2.0f * acc[i][j][h * 2];
                float d1 = cbn[2 * j + 1] - 2.0f * acc[i][j][h * 2 + 1];
                int col = n0 + wn * 32 + j * 8 + tg * 2;
                __nv_bfloat162 v = __halves2bfloat162(__float2bfloat16(d0), __float2bfloat16(d1));
                *(uint32_t*)(g_dmat + (size_t)row * NUM_E + col) = *(uint32_t*)&v;
            }
        }
    }
}

// ---------- pass 2: scan + exact refine (warp per row) ----------
__global__ __launch_bounds__(256) void refine_kernel(const float* __restrict__ z,
                                                     const float* __restrict__ cb) {
    __shared__ float zrow[8][256];
    const int bid = blockIdx.x, tid = threadIdx.x;
    const int w = tid >> 5, lane = tid & 31;
    const int r0 = bid * 8, b = r0 >> 10, hw0 = r0 & 1023;
    for (int e = tid; e < 2048; e += 256) {
        int rr = e & 7, c = e >> 3;
        zrow[rr][c] = z[(size_t)b * 262144 + (size_t)c * 1024 + hw0 + rr];
    }
    __syncthreads();
    const int row = r0 + w;

    float zn2 = 0.f;
    #pragma unroll
    for (int i = 0; i < 8; i++) { float v = zrow[w][lane + 32 * i]; zn2 += v * v; }
    #pragma unroll
    for (int o = 16; o; o >>= 1) zn2 += __shfl_xor_sync(0xffffffffu, zn2, o);

    const __nv_bfloat16* drow = g_dmat + (size_t)row * NUM_E;
    float dv[32];
    float dmin = 3.4e38f;
    #pragma unroll
    for (int i = 0; i < 32; i++) {
        dv[i] = __bfloat162float(drow[lane + 32 * i]);
        dmin = fminf(dmin, dv[i]);
    }
    #pragma unroll
    for (int o = 16; o; o >>= 1) dmin = fminf(dmin, __shfl_xor_sync(0xffffffffu, dmin, o));

    float wmax = sqrtf(__uint_as_float(g_wmaxbits));      // max ||e||
    float T = dmin + 0.025f * sqrtf(zn2) * wmax + 8.0f;   // >3x proven bound

    unsigned long long best = ~0ull;
    #pragma unroll 1
    for (int i = 0; i < 32; i++) {
        unsigned mset = __ballot_sync(0xffffffffu, dv[i] <= T);
        while (mset) {
            int src = __ffs(mset) - 1; mset &= mset - 1;
            int kc = src + 32 * i;
            const float* erow = cb + (size_t)kc * EDIM;
            float s = 0.f;
            #pragma unroll
            for (int jj = 0; jj < 8; jj++)
                s += zrow[w][lane + 32 * jj] * __ldg(&erow[lane + 32 * jj]);
            #pragma unroll
            for (int o = 16; o; o >>= 1) s += __shfl_xor_sync(0xffffffffu, s, o);
            float dist = __ldg(&g_cbnorm[kc]) - 2.0f * s;
            unsigned long long key = ((unsigned long long)ordf(dist) << 32) | (unsigned)kc;
            if (key < best) best = key;
        }
    }
    if (lane == 0) g_idx[row] = (int)(best & 0xFFFFFFFFu);
}

// ---------- outputs: quant gather (blocks < 8192), one-hot scatter (rest) ----------
__global__ __launch_bounds__(256) void finish_kernel(float* __restrict__ oh, float* __restrict__ oq) {
    int bid = blockIdx.x, t = threadIdx.x;
    if (bid < 8192) {
        int i = bid * 256 + t;
        int flat = i * 4;
        int hw = flat & 1023, c = (flat >> 10) & 255, b = flat >> 18;
        int r0 = b * 1024 + hw;
        int4 idx4;
        idx4.x = g_idx[r0]; idx4.y = g_idx[r0 + 1]; idx4.z = g_idx[r0 + 2]; idx4.w = g_idx[r0 + 3];
        const float* rowp = &g_cbT[(size_t)c * NUM_E];
        float4 v;
        v.x = rowp[idx4.x]; v.y = rowp[idx4.y]; v.z = rowp[idx4.z]; v.w = rowp[idx4.w];
        *(float4*)&oq[flat] = v;
    } else {
        int row = (bid - 8192) * 256 + t;
        oh[(size_t)row * NUM_E + g_idx[row]] = 1.0f;
    }
}

extern "C" void kernel_launch(void* const* d_in, const int* in_sizes, int n_in,
                              void* d_out, int out_size) {
    const float* z  = (const float*)d_in[0];
    const float* cb = (const float*)d_in[1];
    float* out_onehot = (float*)d_out;
    float* out_q      = (float*)d_out + (size_t)NROWS * NUM_E;

    cudaFuncSetAttribute(screen_kernel, cudaFuncAttributeMaxDynamicSharedMemorySize, SMEM_TOTAL);

    cudaMemsetAsync(out_onehot, 0, (size_t)NROWS * NUM_E * sizeof(float));
    prep_cb_kernel<<<NUM_E, 256>>>(cb);
    prep_z_kernel<<<2048, 256>>>(z);
    screen_kernel<<<2048, 256, SMEM_TOTAL>>>();
    refine_kernel<<<NROWS / 8, 256>>>(z, cb);
    finish_kernel<<<8192 + NROWS / 256, 256>>>(out_onehot, out_q);
}